// round 1
// baseline (speedup 1.0000x reference)
#include <cuda_runtime.h>

// Problem shapes (fixed by setup_inputs)
#define BB 64
#define TT 1024
#define JJ 32

// Scratch: per-(b,t) root trajectory (x,y,z). 64*1024*3 floats = 3 MB.
__device__ float d_traj[BB * TT * 3];

// Rotate point p by unit quaternion q=(w,x,y,z): p' = p + w*t + u×t, t = 2*(u×p)
__device__ __forceinline__ void qrotate(float w, float x, float y, float z,
                                        float px, float py, float pz,
                                        float& ox, float& oy, float& oz) {
    float tx = 2.0f * (y * pz - z * py);
    float ty = 2.0f * (z * px - x * pz);
    float tz = 2.0f * (x * py - y * px);
    ox = px + w * tx + (y * tz - z * ty);
    oy = py + w * ty + (z * tx - x * tz);
    oz = pz + w * tz + (x * ty - y * tx);
}

// Kernel 1: per-batch exclusive prefix sum of rotated joint-0 velocities,
// offset by rotated glb_pos[b,0,0].  traj[b,t] = pos_rot[b,0,0] + sum_{s<t} vel_rot[b,s,0]
__global__ void traj_scan_kernel(const float* __restrict__ glb_pos,
                                 const float* __restrict__ glb_vel,
                                 const float* __restrict__ root) {
    __shared__ float sx[2][TT], sy[2][TT], sz[2][TT];
    int b = blockIdx.x;
    int t = threadIdx.x;  // 0..1023

    float vx = 0.0f, vy = 0.0f, vz = 0.0f;
    if (t >= 1) {
        int s = t - 1;  // s <= T-2, valid vel index
        const float4 q = __ldg((const float4*)(root + (size_t)(b * TT + s) * 4));
        const float* v = glb_vel + ((size_t)(b * (TT - 1) + s) * JJ) * 3;  // joint 0
        qrotate(q.x, -q.y, -q.z, -q.w, __ldg(v), __ldg(v + 1), __ldg(v + 2), vx, vy, vz);
    }
    sx[0][t] = vx; sy[0][t] = vy; sz[0][t] = vz;
    __syncthreads();

    int src = 0;
    #pragma unroll
    for (int d = 1; d < TT; d <<= 1) {
        int dst = src ^ 1;
        float ax = sx[src][t], ay = sy[src][t], az = sz[src][t];
        if (t >= d) {
            ax += sx[src][t - d];
            ay += sy[src][t - d];
            az += sz[src][t - d];
        }
        sx[dst][t] = ax; sy[dst][t] = ay; sz[dst][t] = az;
        __syncthreads();
        src = dst;
    }

    // base = rotate(inv[b,0], glb_pos[b,0,0])
    const float4 q0 = __ldg((const float4*)(root + (size_t)b * TT * 4));
    const float* p0 = glb_pos + ((size_t)b * TT * JJ) * 3;
    float px, py, pz;
    qrotate(q0.x, -q0.y, -q0.z, -q0.w, __ldg(p0), __ldg(p0 + 1), __ldg(p0 + 2), px, py, pz);

    float* o = d_traj + (size_t)(b * TT + t) * 3;
    o[0] = px + sx[src][t];
    o[1] = py + sy[src][t];
    o[2] = pz + sz[src][t];
}

// Kernel 2: elementwise over (b,t,j).
__global__ void main_kernel(const float* __restrict__ glb_pos,
                            const float* __restrict__ glb_rot,
                            const float* __restrict__ root,
                            float* __restrict__ out) {
    int idx = blockIdx.x * blockDim.x + threadIdx.x;  // 0 .. B*T*J-1
    if (idx >= BB * TT * JJ) return;
    int pair = idx >> 5;  // (b*T + t), since J == 32

    // inv root quaternion (broadcast across the 32 joints of this warp-half)
    const float4 q = __ldg((const float4*)(root + (size_t)pair * 4));
    float w = q.x, x = -q.y, y = -q.z, z = -q.w;

    // --- position path ---
    const float* p = glb_pos + (size_t)idx * 3;
    float px, py, pz;
    qrotate(w, x, y, z, __ldg(p), __ldg(p + 1), __ldg(p + 2), px, py, pz);

    const float* tr = d_traj + (size_t)pair * 3;
    float trx = tr[0], trz = tr[2];  // xz mask: y gets nothing

    float* op = out + (size_t)idx * 3;
    op[0] = px + trx;
    op[1] = py;
    op[2] = pz + trz;

    // --- rotation path: standardize(inv ⊗ glb_rot) ---
    const float4 g = __ldg((const float4*)(glb_rot + (size_t)idx * 4));
    float rw = w * g.x - x * g.y - y * g.z - z * g.w;
    float rx = w * g.y + x * g.x + y * g.w - z * g.z;
    float ry = w * g.z - x * g.w + y * g.x + z * g.y;
    float rz = w * g.w + x * g.z - y * g.y + z * g.x;
    if (rw < 0.0f) { rw = -rw; rx = -rx; ry = -ry; rz = -rz; }

    float4* orr = (float4*)(out + (size_t)BB * TT * JJ * 3 + (size_t)idx * 4);
    *orr = make_float4(rw, rx, ry, rz);
}

extern "C" void kernel_launch(void* const* d_in, const int* in_sizes, int n_in,
                              void* d_out, int out_size) {
    const float* glb_pos = (const float*)d_in[0];
    const float* glb_rot = (const float*)d_in[1];
    const float* glb_vel = (const float*)d_in[2];
    const float* root    = (const float*)d_in[3];
    float* out = (float*)d_out;

    traj_scan_kernel<<<BB, TT>>>(glb_pos, glb_vel, root);

    const int total = BB * TT * JJ;
    const int threads = 256;
    main_kernel<<<(total + threads - 1) / threads, threads>>>(glb_pos, glb_rot, root, out);
}